// round 1
// baseline (speedup 1.0000x reference)
#include <cuda_runtime.h>
#include <math.h>

#define B_   32
#define T_   512
#define E_   256
#define H_   512
#define KTOT 768
#define L_   50
#define NB   128
#define NT   256

// ---------------- device globals (scratch; no allocations allowed) ----------
__device__ float g_hbuf[2 * B_ * H_];           // double-buffered h state
__device__ float g_Y[B_ * T_ * H_];             // masked LSTM outputs (32 MB)
__device__ float g_acc[B_];                     // per-sequence xent sums
__device__ unsigned g_bar_cnt;                  // global barrier counter
__device__ volatile unsigned g_bar_gen;         // global barrier generation

// ---------------- smem layout (bytes) ---------------------------------------
#define S2_OFF    0
#define S2_BYTES  (KTOT * 17 * 8)               // [768][34] floats (pairs of b), pad 34
#define WS_OFF    (S2_OFF + S2_BYTES)           // 104448
#define WS_BYTES  (KTOT * 16 * 4)               // W slice [768][16]
#define ZR_OFF    (WS_OFF + WS_BYTES)           // 153600
#define ZR_BYTES  (4 * 16 * 32 * 4)             // partials [ksec][c][b]
#define CS_OFF    (ZR_OFF + ZR_BYTES)           // 161792
#define CS_BYTES  (128 * 4)                     // c-state [b][jj]
#define BS_OFF    (CS_OFF + CS_BYTES)           // 162304
#define SMEM_TOTAL (BS_OFF + 64)                // 162368

__device__ __forceinline__ unsigned long long ffma2_(unsigned long long a,
                                                     unsigned long long b,
                                                     unsigned long long c) {
    unsigned long long d;
    asm("fma.rn.f32x2 %0, %1, %2, %3;" : "=l"(d) : "l"(a), "l"(b), "l"(c));
    return d;
}

__device__ __forceinline__ unsigned long long splat2_(float x) {
    unsigned long long r;
    unsigned xi = __float_as_uint(x);
    asm("mov.b64 %0, {%1, %1};" : "=l"(r) : "r"(xi));
    return r;
}

// ---------------- persistent recurrent kernel -------------------------------
__global__ void __launch_bounds__(NT, 1)
lstm_kernel(const int* __restrict__ q, const int* __restrict__ lengths,
            const float* __restrict__ we, const float* __restrict__ W,
            const float* __restrict__ bvec)
{
    extern __shared__ char smem[];
    float* Sw   = (float*)(smem + S2_OFF);      // [k][34] (x rows 0..255, h rows 256..767)
    float* Ws   = (float*)(smem + WS_OFF);      // [k][16]
    float* zred = (float*)(smem + ZR_OFF);      // [ks][c][32]
    float* cs   = (float*)(smem + CS_OFF);      // [b*4+jj]
    float* bs   = (float*)(smem + BS_OFF);      // [16]

    const int tid = threadIdx.x;
    const int bid = blockIdx.x;
    const int hd0 = bid << 2;                   // 4 h-dims per block

    // one-time: load W slice (cols {g*512 + hd0 + jj}) and bias
    for (int idx = tid; idx < KTOT * 16; idx += NT) {
        int k = idx >> 4, c = idx & 15;
        int gcol = ((c >> 2) << 9) + hd0 + (c & 3);
        Ws[idx] = W[k * 2048 + gcol];
    }
    if (tid < 16) bs[tid] = bvec[((tid >> 2) << 9) + hd0 + (tid & 3)];
    if (tid < 128) cs[tid] = 0.f;

    // compute-thread decode: 4 k-sections x (8 b-pair groups x 8 col-pair groups)
    const int ksec = tid >> 6;                  // 0..3
    const int o    = tid & 63;
    const int c2   = o & 7;                     // col pair: cols 2c2, 2c2+1
    const int p2   = o >> 3;                    // b-pairs p2 and p2+8
    __syncthreads();

    for (int t = 0; t < T_; ++t) {
        const float* hprev = g_hbuf + (t & 1) * (B_ * H_);
        float* hnext       = g_hbuf + ((t + 1) & 1) * (B_ * H_);

        // ---- stage x (embedding gather): rows k=0..255 ----
        #pragma unroll 4
        for (int b = 0; b < 32; ++b) {
            int row = __ldg(&q[(b << 9) + t]);
            Sw[tid * 34 + b] = __ldg(&we[(row << 8) + tid]);
        }
        // ---- stage h_prev: rows k=256..767 ----
        #pragma unroll 4
        for (int i = 0; i < 64; ++i) {
            int idx = (i << 8) + tid;           // = b*512 + k
            int b = idx >> 9, k = idx & 511;
            Sw[(256 + k) * 34 + b] = hprev[idx];
        }
        __syncthreads();

        // ---- z = [x;h] @ Wslice  (packed f32x2 FMA) ----
        unsigned long long a00 = 0ull, a01 = 0ull, a10 = 0ull, a11 = 0ull;
        const float* Sk = Sw + (ksec * 192) * 34;
        const float* Wk = Ws + (ksec * 192) * 16;
        #pragma unroll 4
        for (int k = 0; k < 192; ++k) {
            unsigned long long h0 = *(const unsigned long long*)(Sk + k * 34 + 2 * p2);
            unsigned long long h1 = *(const unsigned long long*)(Sk + k * 34 + 2 * p2 + 16);
            float2 w01 = *(const float2*)(Wk + k * 16 + 2 * c2);
            unsigned long long wa = splat2_(w01.x);
            unsigned long long wb = splat2_(w01.y);
            a00 = ffma2_(h0, wa, a00);
            a01 = ffma2_(h0, wb, a01);
            a10 = ffma2_(h1, wa, a10);
            a11 = ffma2_(h1, wb, a11);
        }
        {   // write k-partials: zred[ks][c][b], pair view [ks][c][16]
            unsigned long long* zp = (unsigned long long*)zred;
            zp[(ksec * 16 + 2 * c2    ) * 16 + p2    ] = a00;
            zp[(ksec * 16 + 2 * c2 + 1) * 16 + p2    ] = a01;
            zp[(ksec * 16 + 2 * c2    ) * 16 + p2 + 8] = a10;
            zp[(ksec * 16 + 2 * c2 + 1) * 16 + p2 + 8] = a11;
        }
        __syncthreads();

        // ---- gates + state update (128 threads: b in 0..31, jj in 0..3) ----
        if (tid < 128) {
            int b = tid >> 2, jj = tid & 3;
            float g[4];
            #pragma unroll
            for (int gate = 0; gate < 4; ++gate) {
                int c = (gate << 2) + jj;
                float s = bs[c];
                #pragma unroll
                for (int ks = 0; ks < 4; ++ks) s += zred[((ks << 4) + c) * 32 + b];
                g[gate] = s;
            }
            float i_ = 1.f / (1.f + expf(-g[0]));
            float jt = tanhf(g[1]);
            float f_ = 1.f / (1.f + expf(-(g[2] + 1.f)));   // forget bias 1.0
            float o_ = 1.f / (1.f + expf(-g[3]));
            float cold = cs[tid];
            float cnew = cold * f_ + i_ * jt;
            float hnew = tanhf(cnew) * o_;
            bool m = t < __ldg(&lengths[b]);
            int hd = hd0 + jj;
            float hold = Sw[(256 + hd) * 34 + b];            // staged h_prev
            cs[tid] = m ? cnew : cold;
            hnext[(b << 9) + hd] = m ? hnew : hold;          // state carried past length
            g_Y[((b << 9) + t) * 512 + hd] = m ? hnew : 0.f; // dynamic_rnn output
        }
        __syncthreads();

        // ---- grid-wide sense barrier ----
        if (tid == 0) {
            __threadfence();
            unsigned gen = g_bar_gen;
            if (atomicAdd(&g_bar_cnt, 1u) == NB - 1) {
                *(volatile unsigned*)&g_bar_cnt = 0u;
                __threadfence();
                g_bar_gen = gen + 1;
            } else {
                while (g_bar_gen == gen) { __nanosleep(40); }
                __threadfence();
            }
        }
        __syncthreads();
    }
}

// ---------------- init: zero h state + accumulators -------------------------
__global__ void init_kernel() {
    int i = blockIdx.x * blockDim.x + threadIdx.x;
    if (i < B_) g_acc[i] = 0.f;
    for (int j = i; j < 2 * B_ * H_; j += blockDim.x * gridDim.x) g_hbuf[j] = 0.f;
}

// ---------------- projection + masked xent per (b,t) ------------------------
__global__ void loss_kernel(const int* __restrict__ a, const int* __restrict__ lengths,
                            const float* __restrict__ pW, const float* __restrict__ pb)
{
    __shared__ float ys[512];
    __shared__ float lg[64];
    int r = blockIdx.x;
    int b = r >> 9, t = r & 511;
    if (t >= __ldg(&lengths[b])) return;        // masked row: zero contribution
    int tid = threadIdx.x;                      // 64 threads
    const float4* y4 = (const float4*)(g_Y + r * 512);
    ((float4*)ys)[tid]      = y4[tid];
    ((float4*)ys)[tid + 64] = y4[tid + 64];
    __syncthreads();
    float v = -1e30f;
    if (tid < 50) {
        float s = __ldg(&pb[tid]);
        #pragma unroll 8
        for (int h = 0; h < 512; ++h) s += ys[h] * __ldg(&pW[h * 50 + tid]);
        v = fmaxf(s, 0.f);                      // relu
    }
    lg[tid] = v;
    __syncthreads();
    if (tid == 0) {
        float mx = lg[0];
        for (int l = 1; l < 50; ++l) mx = fmaxf(mx, lg[l]);
        float se = 0.f;
        for (int l = 0; l < 50; ++l) se += expf(lg[l] - mx);
        float lse = logf(se) + mx;
        int lab = a[r];
        atomicAdd(&g_acc[b], lse - lg[lab]);    // -logp[label]
    }
}

// ---------------- final scalar reduction -------------------------------------
__global__ void final_kernel(const int* __restrict__ lengths, float* __restrict__ out) {
    if (threadIdx.x == 0) {
        float s = 0.f;
        for (int b = 0; b < B_; ++b) s += g_acc[b] / (float)lengths[b];
        out[0] = s * (1.f / (float)B_);
    }
}

// ---------------- launch ------------------------------------------------------
extern "C" void kernel_launch(void* const* d_in, const int* in_sizes, int n_in,
                              void* d_out, int out_size) {
    const int*   q       = (const int*)d_in[0];
    const int*   a       = (const int*)d_in[1];
    const int*   lengths = (const int*)d_in[2];
    const float* we      = (const float*)d_in[3];
    const float* W       = (const float*)d_in[4];
    const float* bvec    = (const float*)d_in[5];
    const float* pW      = (const float*)d_in[6];
    const float* pb      = (const float*)d_in[7];
    float* out = (float*)d_out;

    cudaFuncSetAttribute(lstm_kernel, cudaFuncAttributeMaxDynamicSharedMemorySize,
                         SMEM_TOTAL);

    init_kernel<<<32, 256>>>();
    lstm_kernel<<<NB, NT, SMEM_TOTAL>>>(q, lengths, we, W, bvec);
    loss_kernel<<<B_ * T_, 64>>>(a, lengths, pW, pb);
    final_kernel<<<1, 32>>>(lengths, out);
}

// round 3
// speedup vs baseline: 1.6683x; 1.6683x over previous
#include <cuda_runtime.h>
#include <math.h>
#include <stdint.h>

#define B_   32
#define T_   512
#define E_   256
#define H_   512
#define L_   50
#define NB   128
#define NT   256

#define PADX 34      // x rows: [256][34] floats
#define PADH 36      // h rows: [512][36] floats (row stride 144B, 16B-aligned)

// ---------------- device globals ---------------------------------------------
__device__ __align__(16) float g_hT[2 * H_ * B_];   // transposed h state [buf][hd][b]
__device__ __align__(16) float g_Y[T_ * H_ * B_];   // outputs [t][hd][b]
__device__ float g_acc[B_];
__device__ unsigned g_bar_cnt;
__device__ volatile unsigned g_bar_gen;

// ---------------- smem layout (floats) ----------------------------------------
#define SWH_OFF  0                         // [512][36]
#define XB_OFF   (SWH_OFF + 512*PADH)      // 18432 : 2 x [256][34]
#define WS_OFF   (XB_OFF + 2*256*PADX)     // +17408 = 35840 : [768][16]
#define ZR_OFF   (WS_OFF + 768*16)         // +12288 = 48128 : [4][16][32]
#define CS_OFF   (ZR_OFF + 2048)           // 50176 : [128]
#define BS_OFF   (CS_OFF + 128)            // 50304 : [16]
#define QS_OFF   (BS_OFF + 16)             // 50320 : [2][32] ints
#define SM_FLOATS (QS_OFF + 64)            // 50384
#define SMEM_TOTAL (SM_FLOATS * 4)         // 201536 B

__device__ __forceinline__ unsigned long long ffma2_(unsigned long long a,
                                                     unsigned long long b,
                                                     unsigned long long c) {
    unsigned long long d;
    asm("fma.rn.f32x2 %0, %1, %2, %3;" : "=l"(d) : "l"(a), "l"(b), "l"(c));
    return d;
}
__device__ __forceinline__ unsigned long long splat2_(float x) {
    unsigned long long r; unsigned xi = __float_as_uint(x);
    asm("mov.b64 %0, {%1, %1};" : "=l"(r) : "r"(xi));
    return r;
}
__device__ __forceinline__ void cp4(uint32_t dst, const void* src) {
    asm volatile("cp.async.ca.shared.global [%0], [%1], 4;" :: "r"(dst), "l"(src));
}
__device__ __forceinline__ void cp16(uint32_t dst, const void* src) {
    asm volatile("cp.async.cg.shared.global [%0], [%1], 16;" :: "r"(dst), "l"(src));
}
__device__ __forceinline__ void cp_commit() { asm volatile("cp.async.commit_group;"); }
__device__ __forceinline__ void cp_wait_all() { asm volatile("cp.async.wait_all;" ::: "memory"); }

// ---------------- persistent recurrent kernel ---------------------------------
__global__ void __launch_bounds__(NT, 1)
lstm_kernel(const int* __restrict__ q, const int* __restrict__ lengths,
            const float* __restrict__ we, const float* __restrict__ W,
            const float* __restrict__ bvec)
{
    extern __shared__ float sm[];
    float* Swh  = sm + SWH_OFF;
    float* Xb   = sm + XB_OFF;
    float* Ws   = sm + WS_OFF;
    float* zred = sm + ZR_OFF;
    float* cs   = sm + CS_OFF;
    float* bs   = sm + BS_OFF;
    int*   qs   = (int*)(sm + QS_OFF);
    const uint32_t sm_u32 = (uint32_t)__cvta_generic_to_shared(sm);

    const int tid = threadIdx.x;
    const int bid = blockIdx.x;
    const int hd0 = bid << 2;

    // ---- prologue: W slice, bias, zero h smem / c state, q0/q1, acc ----
    for (int idx = tid; idx < 768 * 16; idx += NT) {
        int k = idx >> 4, c = idx & 15;
        int gcol = ((c >> 2) << 9) + hd0 + (c & 3);
        Ws[idx] = W[k * 2048 + gcol];
    }
    if (tid < 16) bs[tid] = bvec[((tid >> 2) << 9) + hd0 + (tid & 3)];
    if (tid < 128) cs[tid] = 0.f;
    for (int i = tid; i < 512 * PADH; i += NT) Swh[i] = 0.f;
    if (tid < 32) {
        qs[tid]      = __ldg(&q[(tid << 9)]);
        qs[32 + tid] = __ldg(&q[(tid << 9) + 1]);
    }
    if (bid < 32 && tid == 0) g_acc[bid] = 0.f;
    __syncthreads();

    // stage x0 into Xb[0]
    {
        uint32_t dbase = sm_u32 + (uint32_t)((XB_OFF + tid * PADX) * 4);
        #pragma unroll 8
        for (int b = 0; b < 32; ++b) {
            int row = qs[b];
            cp4(dbase + b * 4, we + (((size_t)row) << 8) + tid);
        }
    }
    cp_commit(); cp_wait_all();
    __syncthreads();

    const int ksec = tid >> 6;          // 0..3
    const int o    = tid & 63;
    const int c2   = o & 7;
    const int p2   = o >> 3;            // 0..7

    // lane decode for h staging (16B copies)
    const int wrp  = tid >> 5, lane = tid & 31;
    const int hb0  = lane & 7, hkq = lane >> 3;

    for (int t = 0; t < T_; ++t) {
        // ---- issue async copies: x_{t+1} prefetch + h_t stage ----
        if (t + 1 < T_) {
            int nb = (t + 1) & 1;
            uint32_t dbase = sm_u32 + (uint32_t)((XB_OFF + nb * 256 * PADX + tid * PADX) * 4);
            const int* qrow = qs + nb * 32;
            #pragma unroll 8
            for (int b = 0; b < 32; ++b) {
                int row = qrow[b];
                cp4(dbase + b * 4, we + (((size_t)row) << 8) + tid);
            }
        }
        if (t > 0) {
            const float* hsrc = g_hT + (t & 1) * (H_ * B_);
            #pragma unroll
            for (int i = 0; i < 16; ++i) {
                int k = wrp * 64 + i * 4 + hkq;
                cp16(sm_u32 + (uint32_t)((SWH_OFF + k * PADH + 4 * hb0) * 4),
                     hsrc + k * 32 + 4 * hb0);
            }
        }
        cp_commit();

        // ---- x-part GEMM (64 rows) while h copies fly ----
        unsigned long long a00 = 0ull, a01 = 0ull, a10 = 0ull, a11 = 0ull;
        {
            const float* Xc = Xb + (t & 1) * 256 * PADX + (ksec * 64) * PADX;
            const float* Wx = Ws + (ksec * 64) * 16;
            #pragma unroll 8
            for (int i = 0; i < 64; ++i) {
                unsigned long long h0 = *(const unsigned long long*)(Xc + i * PADX + 2 * p2);
                unsigned long long h1 = *(const unsigned long long*)(Xc + i * PADX + 2 * p2 + 16);
                float2 w01 = *(const float2*)(Wx + i * 16 + 2 * c2);
                unsigned long long wa = splat2_(w01.x);
                unsigned long long wb = splat2_(w01.y);
                a00 = ffma2_(h0, wa, a00);
                a01 = ffma2_(h0, wb, a01);
                a10 = ffma2_(h1, wa, a10);
                a11 = ffma2_(h1, wb, a11);
            }
        }
        cp_wait_all();
        __syncthreads();

        // ---- h-part GEMM (128 rows) ----
        {
            const float* Hc = Swh + (ksec * 128) * PADH;
            const float* Wh = Ws + (256 + ksec * 128) * 16;
            #pragma unroll 8
            for (int i = 0; i < 128; ++i) {
                unsigned long long h0 = *(const unsigned long long*)(Hc + i * PADH + 2 * p2);
                unsigned long long h1 = *(const unsigned long long*)(Hc + i * PADH + 2 * p2 + 16);
                float2 w01 = *(const float2*)(Wh + i * 16 + 2 * c2);
                unsigned long long wa = splat2_(w01.x);
                unsigned long long wb = splat2_(w01.y);
                a00 = ffma2_(h0, wa, a00);
                a01 = ffma2_(h0, wb, a01);
                a10 = ffma2_(h1, wa, a10);
                a11 = ffma2_(h1, wb, a11);
            }
        }
        {
            unsigned long long* zp = (unsigned long long*)zred;
            zp[(ksec * 16 + 2 * c2    ) * 16 + p2    ] = a00;
            zp[(ksec * 16 + 2 * c2 + 1) * 16 + p2    ] = a01;
            zp[(ksec * 16 + 2 * c2    ) * 16 + p2 + 8] = a10;
            zp[(ksec * 16 + 2 * c2 + 1) * 16 + p2 + 8] = a11;
        }
        __syncthreads();

        // ---- gates + state update ----
        if (tid < 128) {
            int jj = tid >> 5, b = tid & 31;
            float g[4];
            #pragma unroll
            for (int gate = 0; gate < 4; ++gate) {
                int c = (gate << 2) + jj;
                float s = bs[c];
                #pragma unroll
                for (int ks = 0; ks < 4; ++ks) s += zred[((ks << 4) + c) * 32 + b];
                g[gate] = s;
            }
            float i_ = 1.f / (1.f + expf(-g[0]));
            float jt = tanhf(g[1]);
            float f_ = 1.f / (1.f + expf(-(g[2] + 1.f)));
            float o_ = 1.f / (1.f + expf(-g[3]));
            int ci = tid;
            float cold = cs[ci];
            float cnew = cold * f_ + i_ * jt;
            float hnew = tanhf(cnew) * o_;
            bool m = t < __ldg(&lengths[b]);
            int hd = hd0 + jj;
            float hold = Swh[hd * PADH + b];
            cs[ci] = m ? cnew : cold;
            g_hT[((t + 1) & 1) * (H_ * B_) + hd * 32 + b] = m ? hnew : hold;
            g_Y[t * (H_ * B_) + hd * 32 + b] = m ? hnew : 0.f;
        } else if (tid < 160 && t + 2 < T_) {
            int b = tid - 128;
            qs[(t & 1) * 32 + b] = __ldg(&q[(b << 9) + t + 2]);
        }
        __syncthreads();

        // ---- grid barrier ----
        if (tid == 0) {
            __threadfence();
            unsigned gen = g_bar_gen;
            if (atomicAdd(&g_bar_cnt, 1u) == NB - 1) {
                *(volatile unsigned*)&g_bar_cnt = 0u;
                __threadfence();
                g_bar_gen = gen + 1;
            } else {
                while (g_bar_gen == gen) {}
                __threadfence();
            }
        }
        __syncthreads();
    }
}

// ---------------- loss kernel: one block per t --------------------------------
#define LS_YS   0                 // [512][32] = 16384 floats
#define LS_PW   16384             // [512][50] = 25600
#define LS_LG   (16384 + 25600)   // [50][32] = 1600
#define LS_FLOATS (LS_LG + 1600)
#define LOSS_SMEM (LS_FLOATS * 4) // 174336 B

__global__ void __launch_bounds__(256, 1)
loss_kernel(const int* __restrict__ a, const int* __restrict__ lengths,
            const float* __restrict__ pW, const float* __restrict__ pb)
{
    extern __shared__ float ls[];
    float* ys  = ls + LS_YS;
    float* pWs = ls + LS_PW;
    float* lg  = ls + LS_LG;
    const int t = blockIdx.x;
    const int tid = threadIdx.x;

    // load y tile [512][32] and pW [512][50]
    {
        const float4* src = (const float4*)(g_Y + (size_t)t * (H_ * B_));
        float4* dst = (float4*)ys;
        #pragma unroll
        for (int i = 0; i < 16; ++i) dst[tid + i * 256] = src[tid + i * 256];
        const float4* ps = (const float4*)pW;
        float4* pd = (float4*)pWs;
        #pragma unroll
        for (int i = 0; i < 25; ++i) pd[tid + i * 256] = ps[tid + i * 256];
    }
    __syncthreads();

    // logits: thread = (b = tid&31, l0 = tid>>5); l = l0 + 8j
    {
        int b = tid & 31, l0 = tid >> 5;
        for (int l = l0; l < 50; l += 8) {
            float s = __ldg(&pb[l]);
            #pragma unroll 8
            for (int h = 0; h < 512; ++h) s += ys[h * 32 + b] * pWs[h * 50 + l];
            lg[l * 32 + b] = fmaxf(s, 0.f);
        }
    }
    __syncthreads();

    if (tid < 32) {
        int b = tid;
        if (t < __ldg(&lengths[b])) {
            float mx = lg[b];
            #pragma unroll
            for (int l = 1; l < 50; ++l) mx = fmaxf(mx, lg[l * 32 + b]);
            float se = 0.f;
            #pragma unroll
            for (int l = 0; l < 50; ++l) se += expf(lg[l * 32 + b] - mx);
            float lse = logf(se) + mx;
            int lab = __ldg(&a[(b << 9) + t]);
            atomicAdd(&g_acc[b], lse - lg[lab * 32 + b]);
        }
    }
}

// ---------------- final scalar -------------------------------------------------
__global__ void final_kernel(const int* __restrict__ lengths, float* __restrict__ out) {
    if (threadIdx.x == 0) {
        float s = 0.f;
        for (int b = 0; b < B_; ++b) s += g_acc[b] / (float)lengths[b];
        out[0] = s * (1.f / (float)B_);
    }
}

// ---------------- launch --------------------------------------------------------
extern "C" void kernel_launch(void* const* d_in, const int* in_sizes, int n_in,
                              void* d_out, int out_size) {
    const int*   q       = (const int*)d_in[0];
    const int*   a       = (const int*)d_in[1];
    const int*   lengths = (const int*)d_in[2];
    const float* we      = (const float*)d_in[3];
    const float* W       = (const float*)d_in[4];
    const float* bvec    = (const float*)d_in[5];
    const float* pW      = (const float*)d_in[6];
    const float* pb      = (const float*)d_in[7];
    float* out = (float*)d_out;

    cudaFuncSetAttribute(lstm_kernel, cudaFuncAttributeMaxDynamicSharedMemorySize,
                         SMEM_TOTAL);
    cudaFuncSetAttribute(loss_kernel, cudaFuncAttributeMaxDynamicSharedMemorySize,
                         LOSS_SMEM);

    lstm_kernel<<<NB, NT, SMEM_TOTAL>>>(q, lengths, we, W, bvec);
    loss_kernel<<<T_, 256, LOSS_SMEM>>>(a, lengths, pW, pb);
    final_kernel<<<1, 32>>>(lengths, out);
}

// round 4
// speedup vs baseline: 1.9131x; 1.1467x over previous
#include <cuda_runtime.h>
#include <math.h>
#include <stdint.h>

#define B_   32
#define T_   512
#define E_   256
#define H_   512
#define L_   50
#define NB   128
#define NT   256

typedef unsigned long long ull;

// ---------------- device globals -----------------------------------------------
__device__ __align__(16) float g_hT[2 * H_ * B_];        // h state [buf][hd][b]
__device__ __align__(16) float g_Y[T_ * H_ * B_];        // outputs [t][hd][b]
__device__ __align__(16) float g_Zx[(size_t)T_ * 2048 * B_]; // precomputed xW+b [t][col][b]
__device__ float g_acc[B_];
__device__ unsigned g_bar_cnt;
__device__ volatile unsigned g_bar_gen;

// ---------------- helpers --------------------------------------------------------
__device__ __forceinline__ ull ffma2_(ull a, ull b, ull c) {
    ull d;
    asm("fma.rn.f32x2 %0, %1, %2, %3;" : "=l"(d) : "l"(a), "l"(b), "l"(c));
    return d;
}
__device__ __forceinline__ ull splat2_(float x) {
    ull r; unsigned xi = __float_as_uint(x);
    asm("mov.b64 %0, {%1, %1};" : "=l"(r) : "r"(xi));
    return r;
}
__device__ __forceinline__ void cp16(uint32_t dst, const void* src) {
    asm volatile("cp.async.cg.shared.global [%0], [%1], 16;" :: "r"(dst), "l"(src));
}
__device__ __forceinline__ void cp_commit() { asm volatile("cp.async.commit_group;"); }
#define CP_WAIT(N) asm volatile("cp.async.wait_group %0;" :: "n"(N) : "memory")

// ================================================================================
// Phase A: zx precompute.  grid = (T_ * 4), block computes [32 x 512] cols for one t
// ================================================================================
#define ZXD_OFF  0                     // XD [256 k][32 b] floats
#define ZWB_OFF  (256*32)              // 8192 : WB 3 x [16 k][512 c]
#define ZX_SMEM  ((8192 + 3*8192) * 4) // 131072 B
#define XT_PAD   261

__global__ void __launch_bounds__(256, 1)
zx_kernel(const int* __restrict__ q, const float* __restrict__ we,
          const float* __restrict__ W, const float* __restrict__ bvec)
{
    extern __shared__ float sm[];
    float* XD = sm + ZXD_OFF;          // [k][b]
    float* WB = sm + ZWB_OFF;          // 3 bufs
    float* XT = sm + ZWB_OFF;          // transpose scratch [32][261] (dead before WB use)
    const uint32_t smu = (uint32_t)__cvta_generic_to_shared(sm);
    __shared__ int qrow[32];

    const int tid = threadIdx.x;
    const int t   = blockIdx.x >> 2;
    const int c0  = (blockIdx.x & 3) << 9;

    if (tid < 32) qrow[tid] = q[(tid << 9) + t];
    __syncthreads();
    // stage x -> XT[b][k] (coalesced LDG, conflict-free STS)
    #pragma unroll
    for (int i = 0; i < 32; ++i) {
        int idx = tid + (i << 8);
        int b = idx >> 8, k = idx & 255;
        XT[b * XT_PAD + k] = we[(((size_t)qrow[b]) << 8) + k];
    }
    __syncthreads();
    // transpose -> XD[k][b] (conflict-free both sides: 261 % 32 = 5, coprime)
    float xbuf[32];
    #pragma unroll
    for (int i = 0; i < 32; ++i) {
        int idx = tid + (i << 8);
        int k = idx >> 5, b = idx & 31;
        xbuf[i] = XT[b * XT_PAD + k];
    }
    __syncthreads();                   // XT reads done before WB/XD overwrite
    #pragma unroll
    for (int i = 0; i < 32; ++i) {
        int idx = tid + (i << 8);
        int k = idx >> 5, b = idx & 31;
        XD[k * 32 + b] = xbuf[i];
    }
    __syncthreads();

    // W chunk staging lambda-ish
    const int bq = tid & 3;            // batches bq*8..+8  (4 bpairs)
    const int cq = tid >> 2;           // cols  cq*8..+8

    // prefetch chunks 0,1
    #pragma unroll
    for (int pc = 0; pc < 2; ++pc) {
        int buf = pc;
        #pragma unroll
        for (int i = 0; i < 8; ++i) {
            int u = tid + (i << 8);
            int kk = u >> 7, c16 = u & 127;
            cp16(smu + (uint32_t)((ZWB_OFF + buf * 8192 + kk * 512 + (c16 << 2)) * 4),
                 W + ((size_t)(pc * 16 + kk)) * 2048 + c0 + (c16 << 2));
        }
        cp_commit();
    }

    ull acc[4][8];
    #pragma unroll
    for (int i = 0; i < 4; ++i)
        #pragma unroll
        for (int j = 0; j < 8; ++j) acc[i][j] = 0ull;

    for (int kc = 0; kc < 16; ++kc) {
        if (kc < 15) { CP_WAIT(1); } else { CP_WAIT(0); }
        __syncthreads();
        const float* Wc = WB + (kc % 3) * 8192;
        const float* Xc = XD + kc * 16 * 32;
        #pragma unroll
        for (int kk = 0; kk < 16; ++kk) {
            ulonglong2 xa = *(const ulonglong2*)(Xc + kk * 32 + bq * 8);
            ulonglong2 xb = *(const ulonglong2*)(Xc + kk * 32 + bq * 8 + 4);
            float4 w0 = *(const float4*)(Wc + kk * 512 + cq * 8);
            float4 w1 = *(const float4*)(Wc + kk * 512 + cq * 8 + 4);
            ull ws[8];
            ws[0] = splat2_(w0.x); ws[1] = splat2_(w0.y);
            ws[2] = splat2_(w0.z); ws[3] = splat2_(w0.w);
            ws[4] = splat2_(w1.x); ws[5] = splat2_(w1.y);
            ws[6] = splat2_(w1.z); ws[7] = splat2_(w1.w);
            #pragma unroll
            for (int c = 0; c < 8; ++c) {
                acc[0][c] = ffma2_(xa.x, ws[c], acc[0][c]);
                acc[1][c] = ffma2_(xa.y, ws[c], acc[1][c]);
                acc[2][c] = ffma2_(xb.x, ws[c], acc[2][c]);
                acc[3][c] = ffma2_(xb.y, ws[c], acc[3][c]);
            }
        }
        if (kc + 2 < 16) {
            int buf = (kc + 2) % 3;
            #pragma unroll
            for (int i = 0; i < 8; ++i) {
                int u = tid + (i << 8);
                int kk = u >> 7, c16 = u & 127;
                cp16(smu + (uint32_t)((ZWB_OFF + buf * 8192 + kk * 512 + (c16 << 2)) * 4),
                     W + ((size_t)((kc + 2) * 16 + kk)) * 2048 + c0 + (c16 << 2));
            }
            cp_commit();
        }
    }

    // epilogue: add bias, store [col][b] pairs (coalesced 32B sectors)
    #pragma unroll
    for (int c = 0; c < 8; ++c) {
        int cg = c0 + cq * 8 + c;
        float bb = __ldg(&bvec[cg]);
        float* outp = g_Zx + ((size_t)t * 2048 + cg) * 32 + bq * 8;
        #pragma unroll
        for (int bp = 0; bp < 4; ++bp) {
            union { ull u; float2 f; } v; v.u = acc[bp][c];
            v.f.x += bb; v.f.y += bb;
            *(float2*)(outp + bp * 2) = v.f;
        }
    }
}

// ================================================================================
// Phase B: recurrence.  128 persistent blocks, block owns 4 h-dims (16 z-cols)
// ================================================================================
#define SWH_OFF  0                      // [512 k][32 b]
#define WD_OFF   16384                  // [512 k][16 c] u64 (duplicated W)
#define ZXS_OFF  32768                  // [16 c][32 b]
#define ZR_OFF   33280                  // [8 ks][16 c][32 b]
#define CS_OFF   37376                  // [128]
#define LEN_OFF  37504                  // [32]
#define SMEM_TOTAL ((LEN_OFF + 32) * 4) // 150144 B

__global__ void __launch_bounds__(NT, 1)
lstm_kernel(const int* __restrict__ lengths, const float* __restrict__ W)
{
    extern __shared__ float sm[];
    float* Swh  = sm + SWH_OFF;
    ull*   WDu  = (ull*)(sm + WD_OFF);
    float* zxs  = sm + ZXS_OFF;
    float* zred = sm + ZR_OFF;
    float* cs   = sm + CS_OFF;
    float* ls   = sm + LEN_OFF;
    const uint32_t smu = (uint32_t)__cvta_generic_to_shared(sm);

    const int tid = threadIdx.x;
    const int bid = blockIdx.x;
    const int hd0 = bid << 2;

    // prologue: duplicated W slice (h-part rows 256..767), state zero, lengths
    for (int i = tid; i < 512 * 16; i += NT) {
        int k = i >> 4, c = i & 15;
        float w = W[((size_t)(256 + k)) * 2048 + (((c >> 2) << 9) + hd0 + (c & 3))];
        WDu[i] = splat2_(w);
    }
    for (int i = tid; i < 512 * 32; i += NT) Swh[i] = 0.f;
    if (tid < 128) cs[tid] = 0.f;
    if (tid < 32)  ls[tid] = (float)0, ((int*)ls)[tid] = lengths[tid];
    if (bid < 32 && tid == 0) g_acc[bid] = 0.f;
    __syncthreads();

    const int wid  = tid >> 5, lane = tid & 31;
    const int bg   = lane & 7;          // batches 4bg..+4
    const int cg   = lane >> 3;         // cols 4cg..+4
    const int krow0 = wid << 6;         // warp's 64 k rows
    const int srow  = lane >> 1, spart = lane & 1;

    for (int t = 0; t < T_; ++t) {
        const float* hsrc = g_hT + (t & 1) * (H_ * B_);

        // ---- issue 4 pipelined cp.async groups (warp stages its own rows) ----
        #pragma unroll
        for (int c = 0; c < 4; ++c) {
            if (t > 0) {
                int r = krow0 + (c << 4) + srow;
                int fo = r * 32 + (spart << 4);
                #pragma unroll
                for (int i = 0; i < 4; ++i)
                    cp16(smu + (uint32_t)((SWH_OFF + fo + (i << 2)) * 4),
                         hsrc + fo + (i << 2));
            }
            if (c == 0 && tid < 128) {
                int r = tid >> 3, p = tid & 7;
                const float* src = g_Zx + ((size_t)(t << 2) + (r >> 2)) * 512 * 32
                                   + (size_t)(hd0 + (r & 3)) * 32 + (p << 2);
                cp16(smu + (uint32_t)((ZXS_OFF + r * 32 + (p << 2)) * 4), src);
            }
            cp_commit();
        }

        // ---- h-GEMM: 4 chunks of 16 rows, pipelined against arrivals ----
        ull acc[8];
        #pragma unroll
        for (int i = 0; i < 8; ++i) acc[i] = 0ull;
        #pragma unroll
        for (int c = 0; c < 4; ++c) {
            if      (c == 0) { CP_WAIT(3); }
            else if (c == 1) { CP_WAIT(2); }
            else if (c == 2) { CP_WAIT(1); }
            else             { CP_WAIT(0); }
            __syncwarp();
            const float* Hc = Swh + (krow0 + (c << 4)) * 32;
            const ull*   Wc = WDu + (krow0 + (c << 4)) * 16;
            #pragma unroll
            for (int kk = 0; kk < 16; ++kk) {
                ulonglong2 h2 = *(const ulonglong2*)(Hc + kk * 32 + (bg << 2));
                ulonglong2 w0 = *(const ulonglong2*)(Wc + kk * 16 + (cg << 2));
                ulonglong2 w1 = *(const ulonglong2*)(Wc + kk * 16 + (cg << 2) + 2);
                acc[0] = ffma2_(h2.x, w0.x, acc[0]);
                acc[1] = ffma2_(h2.y, w0.x, acc[1]);
                acc[2] = ffma2_(h2.x, w0.y, acc[2]);
                acc[3] = ffma2_(h2.y, w0.y, acc[3]);
                acc[4] = ffma2_(h2.x, w1.x, acc[4]);
                acc[5] = ffma2_(h2.y, w1.x, acc[5]);
                acc[6] = ffma2_(h2.x, w1.y, acc[6]);
                acc[7] = ffma2_(h2.y, w1.y, acc[7]);
            }
        }
        {   // write partials: zred[wid][col][b] (u64 view)
            ull* zru = (ull*)zred;
            #pragma unroll
            for (int cc = 0; cc < 4; ++cc) {
                int base = ((wid << 4) + (cg << 2) + cc) * 16 + (bg << 1);
                zru[base]     = acc[cc * 2];
                zru[base + 1] = acc[cc * 2 + 1];
            }
        }
        __syncthreads();

        // ---- gates + state update ----
        if (tid < 128) {
            int b = tid & 31, jj = tid >> 5;
            float g[4];
            #pragma unroll
            for (int gate = 0; gate < 4; ++gate) {
                int c = (gate << 2) + jj;
                float s = zxs[c * 32 + b];
                #pragma unroll
                for (int ks = 0; ks < 8; ++ks) s += zred[((ks << 4) + c) * 32 + b];
                g[gate] = s;
            }
            float i_ = 1.f / (1.f + expf(-g[0]));
            float jt = tanhf(g[1]);
            float f_ = 1.f / (1.f + expf(-(g[2] + 1.f)));
            float o_ = 1.f / (1.f + expf(-g[3]));
            float cold = cs[tid];
            float cnew = cold * f_ + i_ * jt;
            float hnew = tanhf(cnew) * o_;
            bool m = t < ((int*)ls)[b];
            int hd = hd0 + jj;
            float hold = Swh[hd * 32 + b];
            cs[tid] = m ? cnew : cold;
            g_hT[((t + 1) & 1) * (H_ * B_) + hd * 32 + b] = m ? hnew : hold;
            g_Y[(size_t)t * (H_ * B_) + hd * 32 + b] = m ? hnew : 0.f;
        }
        __syncthreads();

        // ---- grid barrier ----
        if (tid == 0) {
            __threadfence();
            unsigned gen = g_bar_gen;
            if (atomicAdd(&g_bar_cnt, 1u) == NB - 1) {
                *(volatile unsigned*)&g_bar_cnt = 0u;
                __threadfence();
                g_bar_gen = gen + 1;
            } else {
                while (g_bar_gen == gen) {}
                __threadfence();
            }
        }
        __syncthreads();
    }
}

// ================================================================================
// Phase C: projection + masked xent. one block per t
// ================================================================================
#define LS_YS   0
#define LS_PW   16384
#define LS_LG   (16384 + 25600)
#define LOSS_SMEM ((LS_LG + 1600) * 4)

__global__ void __launch_bounds__(256, 1)
loss_kernel(const int* __restrict__ a, const int* __restrict__ lengths,
            const float* __restrict__ pW, const float* __restrict__ pb)
{
    extern __shared__ float lsm[];
    float* ys  = lsm + LS_YS;
    float* pWs = lsm + LS_PW;
    float* lg  = lsm + LS_LG;
    const int t = blockIdx.x;
    const int tid = threadIdx.x;

    {
        const float4* src = (const float4*)(g_Y + (size_t)t * (H_ * B_));
        float4* dst = (float4*)ys;
        #pragma unroll
        for (int i = 0; i < 16; ++i) dst[tid + i * 256] = src[tid + i * 256];
        const float4* ps = (const float4*)pW;
        float4* pd = (float4*)pWs;
        #pragma unroll
        for (int i = 0; i < 25; ++i) pd[tid + i * 256] = ps[tid + i * 256];
    }
    __syncthreads();

    {
        int b = tid & 31, l0 = tid >> 5;
        for (int l = l0; l < 50; l += 8) {
            float s = __ldg(&pb[l]);
            #pragma unroll 8
            for (int h = 0; h < 512; ++h) s += ys[h * 32 + b] * pWs[h * 50 + l];
            lg[l * 32 + b] = fmaxf(s, 0.f);
        }
    }
    __syncthreads();

    if (tid < 32) {
        int b = tid;
        if (t < __ldg(&lengths[b])) {
            float mx = lg[b];
            #pragma unroll
            for (int l = 1; l < 50; ++l) mx = fmaxf(mx, lg[l * 32 + b]);
            float se = 0.f;
            #pragma unroll
            for (int l = 0; l < 50; ++l) se += expf(lg[l * 32 + b] - mx);
            float lse = logf(se) + mx;
            int lab = __ldg(&a[(b << 9) + t]);
            atomicAdd(&g_acc[b], lse - lg[lab * 32 + b]);
        }
    }
}

__global__ void final_kernel(const int* __restrict__ lengths, float* __restrict__ out) {
    if (threadIdx.x == 0) {
        float s = 0.f;
        for (int b = 0; b < B_; ++b) s += g_acc[b] / (float)lengths[b];
        out[0] = s * (1.f / (float)B_);
    }
}

// ---------------- launch ----------------------------------------------------------
extern "C" void kernel_launch(void* const* d_in, const int* in_sizes, int n_in,
                              void* d_out, int out_size) {
    const int*   q       = (const int*)d_in[0];
    const int*   a       = (const int*)d_in[1];
    const int*   lengths = (const int*)d_in[2];
    const float* we      = (const float*)d_in[3];
    const float* W       = (const float*)d_in[4];
    const float* bvec    = (const float*)d_in[5];
    const float* pW      = (const float*)d_in[6];
    const float* pb      = (const float*)d_in[7];
    float* out = (float*)d_out;

    cudaFuncSetAttribute(zx_kernel, cudaFuncAttributeMaxDynamicSharedMemorySize, ZX_SMEM);
    cudaFuncSetAttribute(lstm_kernel, cudaFuncAttributeMaxDynamicSharedMemorySize, SMEM_TOTAL);
    cudaFuncSetAttribute(loss_kernel, cudaFuncAttributeMaxDynamicSharedMemorySize, LOSS_SMEM);

    zx_kernel<<<T_ * 4, 256, ZX_SMEM>>>(q, we, W, bvec);
    lstm_kernel<<<NB, NT, SMEM_TOTAL>>>(lengths, W);
    loss_kernel<<<T_, 256, LOSS_SMEM>>>(a, lengths, pW, pb);
    final_kernel<<<1, 32>>>(lengths, out);
}

// round 5
// speedup vs baseline: 2.4421x; 1.2765x over previous
#include <cuda_runtime.h>
#include <math.h>
#include <stdint.h>

#define B_   32
#define T_   512
#define E_   256
#define H_   512
#define L_   50
#define NB   128
#define NBG  64      // blocks per batch-group
#define NT   256

typedef unsigned long long ull;

// ---------------- device globals -----------------------------------------------
__device__ __align__(16) float g_hT[2 * 2 * H_ * 16];   // [grp][buf][hd][16b]
__device__ __align__(16) float g_Y[T_ * H_ * B_];       // [t][hd][32b]
__device__ __align__(16) float g_Zx[(size_t)T_ * 2048 * B_]; // [t][col][32b]
__device__ float g_acc[B_];
__device__ unsigned g_barc[2];                          // per-group monotonic counters

// ---------------- helpers --------------------------------------------------------
__device__ __forceinline__ ull ffma2_(ull a, ull b, ull c) {
    ull d;
    asm("fma.rn.f32x2 %0, %1, %2, %3;" : "=l"(d) : "l"(a), "l"(b), "l"(c));
    return d;
}
__device__ __forceinline__ ull splat2_(float x) {
    ull r; unsigned xi = __float_as_uint(x);
    asm("mov.b64 %0, {%1, %1};" : "=l"(r) : "r"(xi));
    return r;
}
__device__ __forceinline__ void cp16(uint32_t dst, const void* src) {
    asm volatile("cp.async.cg.shared.global [%0], [%1], 16;" :: "r"(dst), "l"(src));
}
__device__ __forceinline__ void cp_commit() { asm volatile("cp.async.commit_group;"); }
#define CP_WAIT(N) asm volatile("cp.async.wait_group %0;" :: "n"(N) : "memory")

__device__ __forceinline__ float fsig_(float x) {        // sigmoid, clamped
    x = fminf(fmaxf(x, -30.f), 30.f);
    float e = __expf(-x);
    return __fdividef(1.f, 1.f + e);
}
__device__ __forceinline__ float ftanh_(float x) {       // tanh, clamped
    x = fminf(fmaxf(x, -15.f), 15.f);
    float e = __expf(-2.f * x);
    return __fdividef(1.f - e, 1.f + e);
}

// ================================================================================
// Phase A: zx precompute.  grid = (T_ * 4); also resets barrier counters / acc
// ================================================================================
#define ZXD_OFF  0
#define ZWB_OFF  (256*32)
#define ZX_SMEM  ((8192 + 3*8192) * 4)
#define XT_PAD   261

__global__ void __launch_bounds__(256, 1)
zx_kernel(const int* __restrict__ q, const float* __restrict__ we,
          const float* __restrict__ W, const float* __restrict__ bvec)
{
    extern __shared__ float sm[];
    float* XD = sm + ZXD_OFF;
    float* WB = sm + ZWB_OFF;
    float* XT = sm + ZWB_OFF;
    const uint32_t smu = (uint32_t)__cvta_generic_to_shared(sm);
    __shared__ int qrow[32];

    const int tid = threadIdx.x;
    const int t   = blockIdx.x >> 2;
    const int c0  = (blockIdx.x & 3) << 9;

    if (blockIdx.x == 0) {                    // graph-replay-safe reset
        if (tid < 2)  g_barc[tid] = 0u;
        if (tid < 32) g_acc[tid] = 0.f;
    }

    if (tid < 32) qrow[tid] = q[(tid << 9) + t];
    __syncthreads();
    #pragma unroll
    for (int i = 0; i < 32; ++i) {
        int idx = tid + (i << 8);
        int b = idx >> 8, k = idx & 255;
        XT[b * XT_PAD + k] = we[(((size_t)qrow[b]) << 8) + k];
    }
    __syncthreads();
    float xbuf[32];
    #pragma unroll
    for (int i = 0; i < 32; ++i) {
        int idx = tid + (i << 8);
        int k = idx >> 5, b = idx & 31;
        xbuf[i] = XT[b * XT_PAD + k];
    }
    __syncthreads();
    #pragma unroll
    for (int i = 0; i < 32; ++i) {
        int idx = tid + (i << 8);
        int k = idx >> 5, b = idx & 31;
        XD[k * 32 + b] = xbuf[i];
    }
    __syncthreads();

    const int bq = tid & 3;
    const int cq = tid >> 2;

    #pragma unroll
    for (int pc = 0; pc < 2; ++pc) {
        #pragma unroll
        for (int i = 0; i < 8; ++i) {
            int u = tid + (i << 8);
            int kk = u >> 7, c16 = u & 127;
            cp16(smu + (uint32_t)((ZWB_OFF + pc * 8192 + kk * 512 + (c16 << 2)) * 4),
                 W + ((size_t)(pc * 16 + kk)) * 2048 + c0 + (c16 << 2));
        }
        cp_commit();
    }

    ull acc[4][8];
    #pragma unroll
    for (int i = 0; i < 4; ++i)
        #pragma unroll
        for (int j = 0; j < 8; ++j) acc[i][j] = 0ull;

    for (int kc = 0; kc < 16; ++kc) {
        if (kc < 15) { CP_WAIT(1); } else { CP_WAIT(0); }
        __syncthreads();
        const float* Wc = WB + (kc % 3) * 8192;
        const float* Xc = XD + kc * 16 * 32;
        #pragma unroll
        for (int kk = 0; kk < 16; ++kk) {
            ulonglong2 xa = *(const ulonglong2*)(Xc + kk * 32 + bq * 8);
            ulonglong2 xb = *(const ulonglong2*)(Xc + kk * 32 + bq * 8 + 4);
            float4 w0 = *(const float4*)(Wc + kk * 512 + cq * 8);
            float4 w1 = *(const float4*)(Wc + kk * 512 + cq * 8 + 4);
            ull ws[8];
            ws[0] = splat2_(w0.x); ws[1] = splat2_(w0.y);
            ws[2] = splat2_(w0.z); ws[3] = splat2_(w0.w);
            ws[4] = splat2_(w1.x); ws[5] = splat2_(w1.y);
            ws[6] = splat2_(w1.z); ws[7] = splat2_(w1.w);
            #pragma unroll
            for (int c = 0; c < 8; ++c) {
                acc[0][c] = ffma2_(xa.x, ws[c], acc[0][c]);
                acc[1][c] = ffma2_(xa.y, ws[c], acc[1][c]);
                acc[2][c] = ffma2_(xb.x, ws[c], acc[2][c]);
                acc[3][c] = ffma2_(xb.y, ws[c], acc[3][c]);
            }
        }
        if (kc + 2 < 16) {
            int buf = (kc + 2) % 3;
            #pragma unroll
            for (int i = 0; i < 8; ++i) {
                int u = tid + (i << 8);
                int kk = u >> 7, c16 = u & 127;
                cp16(smu + (uint32_t)((ZWB_OFF + buf * 8192 + kk * 512 + (c16 << 2)) * 4),
                     W + ((size_t)((kc + 2) * 16 + kk)) * 2048 + c0 + (c16 << 2));
            }
            cp_commit();
        }
    }

    #pragma unroll
    for (int c = 0; c < 8; ++c) {
        int cg = c0 + cq * 8 + c;
        float bb = __ldg(&bvec[cg]);
        float* outp = g_Zx + ((size_t)t * 2048 + cg) * 32 + bq * 8;
        #pragma unroll
        for (int bp = 0; bp < 4; ++bp) {
            union { ull u; float2 f; } v; v.u = acc[bp][c];
            v.f.x += bb; v.f.y += bb;
            *(float2*)(outp + bp * 2) = v.f;
        }
    }
}

// ================================================================================
// Phase B: recurrence. 2 groups x 64 blocks; block = 8 h-dims x 32 cols x 16 batches
// ================================================================================
#define SWH_OFF  0                       // [512 k][16 b]
#define WD_OFF   8192                    // [512 k][32 pos] u64 (duplicated, reordered)
#define ZXS_OFF  (8192 + 65536)          // 73728? (floats) -> see below
// float offsets:
#define WD_FLT   8192                    // WD occupies 32768 floats
#define ZXS_FLT  (WD_FLT + 32768)        // 40960 : [32 c][16 b]
#define ZR_FLT   (ZXS_FLT + 512)         // 41472 : [8 ws][32 c][16 b]
#define CS_FLT   (ZR_FLT + 4096)         // 45568 : [128]
#define LEN_FLT  (CS_FLT + 128)          // 45696 : [16] ints
#define SMEM_TOTAL ((LEN_FLT + 16) * 4)  // 182848 B

__global__ void __launch_bounds__(NT, 1)
lstm_kernel(const int* __restrict__ lengths, const float* __restrict__ W)
{
    extern __shared__ float sm[];
    float* Swh  = sm + SWH_OFF;
    ull*   WDu  = (ull*)(sm + WD_FLT);
    float* zxs  = sm + ZXS_FLT;
    float* zred = sm + ZR_FLT;
    float* cs   = sm + CS_FLT;
    int*   ls   = (int*)(sm + LEN_FLT);
    const uint32_t smu = (uint32_t)__cvta_generic_to_shared(sm);

    const int tid = threadIdx.x;
    const int bid = blockIdx.x;
    const int grp = bid >> 6;            // batch group 0/1
    const int gb  = bid & 63;
    const int hd0 = gb << 3;             // 8 h-dims per block

    // prologue: duplicated+reordered W slice (rows 256..767), zero state, lengths
    for (int i = tid; i < 512 * 32; i += NT) {
        int k = i >> 5, c = i & 31;      // c = block col = gate*8 + jj
        int cq = c >> 2, cc = c & 3;
        int pos = ((cc >> 1) << 4) + (cq << 1) + (cc & 1);
        float w = W[((size_t)(256 + k)) * 2048 + (((c >> 3) << 9) + hd0 + (c & 7))];
        WDu[(k << 5) + pos] = splat2_(w);
    }
    for (int i = tid; i < 512 * 16; i += NT) Swh[i] = 0.f;
    if (tid < 128) cs[tid] = 0.f;
    if (tid < 16)  ls[tid] = lengths[(grp << 4) + tid];
    __syncthreads();

    const int wid  = tid >> 5, lane = tid & 31;
    const int bg   = lane & 3;           // batch quad: b = 4bg..4bg+3
    const int cq   = lane >> 2;          // col quad:  c = 4cq..4cq+3
    const int krow0 = wid << 6;
    const int srow  = lane >> 1, spart = lane & 1;

    unsigned* barp = &g_barc[grp];

    for (int t = 0; t < T_; ++t) {
        const float* hsrc = g_hT + (((grp << 1) + (t & 1)) << 13); // *512*16

        // ---- issue 4 pipelined cp.async groups ----
        #pragma unroll
        for (int c = 0; c < 4; ++c) {
            if (t > 0) {
                int r = krow0 + (c << 4) + srow;
                int fo = (r << 4) + (spart << 3);
                cp16(smu + (uint32_t)((SWH_OFF + fo) * 4), hsrc + fo);
                cp16(smu + (uint32_t)((SWH_OFF + fo + 4) * 4), hsrc + fo + 4);
            }
            if (c == 0 && tid < 128) {
                int r = tid >> 2, p = tid & 3;   // col r, 4-float chunk p
                int gcol = ((r >> 3) << 9) + hd0 + (r & 7);
                const float* src = g_Zx + ((size_t)(t << 11) + gcol) * 32
                                   + (grp << 4) + (p << 2);
                cp16(smu + (uint32_t)((ZXS_FLT + (r << 4) + (p << 2)) * 4), src);
            }
            cp_commit();
        }

        // ---- h-GEMM: 4 chunks x 16 rows ----
        ull acc[8];
        #pragma unroll
        for (int i = 0; i < 8; ++i) acc[i] = 0ull;
        #pragma unroll
        for (int c = 0; c < 4; ++c) {
            if      (c == 0) { CP_WAIT(3); }
            else if (c == 1) { CP_WAIT(2); }
            else if (c == 2) { CP_WAIT(1); }
            else             { CP_WAIT(0); }
            __syncwarp();
            const float* Hc = Swh + ((krow0 + (c << 4)) << 4);
            const ull*   Wc = WDu + ((krow0 + (c << 4)) << 5);
            #pragma unroll
            for (int kk = 0; kk < 16; ++kk) {
                ulonglong2 h2 = *(const ulonglong2*)(Hc + (kk << 4) + (bg << 2));
                ulonglong2 w0 = *(const ulonglong2*)(Wc + (kk << 5) + (cq << 1));
                ulonglong2 w1 = *(const ulonglong2*)(Wc + (kk << 5) + 16 + (cq << 1));
                acc[0] = ffma2_(h2.x, w0.x, acc[0]);
                acc[1] = ffma2_(h2.y, w0.x, acc[1]);
                acc[2] = ffma2_(h2.x, w0.y, acc[2]);
                acc[3] = ffma2_(h2.y, w0.y, acc[3]);
                acc[4] = ffma2_(h2.x, w1.x, acc[4]);
                acc[5] = ffma2_(h2.y, w1.x, acc[5]);
                acc[6] = ffma2_(h2.x, w1.y, acc[6]);
                acc[7] = ffma2_(h2.y, w1.y, acc[7]);
            }
        }
        {   // partials: zred[ws][c][16b] as u64 pairs
            ull* zru = (ull*)zred;
            #pragma unroll
            for (int cc = 0; cc < 4; ++cc) {
                int base = (((wid << 5) + (cq << 2) + cc) << 3) + (bg << 1);
                zru[base]     = acc[cc * 2];
                zru[base + 1] = acc[cc * 2 + 1];
            }
        }
        __syncthreads();

        // ---- gates + state update (128 threads: jj 0..7, b 0..15) ----
        if (tid < 128) {
            int b = tid & 15, jj = tid >> 4;
            float g[4];
            #pragma unroll
            for (int gate = 0; gate < 4; ++gate) {
                int c = (gate << 3) + jj;
                float s = zxs[(c << 4) + b];
                #pragma unroll
                for (int ks = 0; ks < 8; ++ks) s += zred[(((ks << 5) + c) << 4) + b];
                g[gate] = s;
            }
            float i_ = fsig_(g[0]);
            float jt = ftanh_(g[1]);
            float f_ = fsig_(g[2] + 1.f);
            float o_ = fsig_(g[3]);
            float cold = cs[tid];
            float cnew = cold * f_ + i_ * jt;
            float hnew = ftanh_(cnew) * o_;
            bool m = t < ls[b];
            int hd = hd0 + jj;
            float hold = Swh[(hd << 4) + b];
            cs[tid] = m ? cnew : cold;
            g_hT[(((grp << 1) + ((t + 1) & 1)) << 13) + (hd << 4) + b] = m ? hnew : hold;
            g_Y[((size_t)(t << 9) + hd) * 32 + (grp << 4) + b] = m ? hnew : 0.f;
        }
        __syncthreads();

        // ---- group barrier: release-arrive + acquire-poll, monotonic ----
        if (tid == 0) {
            asm volatile("red.release.gpu.global.add.u32 [%0], %1;"
                         :: "l"(barp), "r"(1u) : "memory");
            unsigned target = (unsigned)(t + 1) * NBG;
            unsigned v;
            do {
                asm volatile("ld.acquire.gpu.global.u32 %0, [%1];"
                             : "=r"(v) : "l"(barp) : "memory");
            } while (v < target);
        }
        __syncthreads();
    }
}

// ================================================================================
// Phase C: projection + masked xent. one block per t
// ================================================================================
#define LS_YS   0
#define LS_PW   16384
#define LS_LG   (16384 + 25600)
#define LOSS_SMEM ((LS_LG + 1600) * 4)

__global__ void __launch_bounds__(256, 1)
loss_kernel(const int* __restrict__ a, const int* __restrict__ lengths,
            const float* __restrict__ pW, const float* __restrict__ pb)
{
    extern __shared__ float lsm[];
    float* ys  = lsm + LS_YS;
    float* pWs = lsm + LS_PW;
    float* lg  = lsm + LS_LG;
    const int t = blockIdx.x;
    const int tid = threadIdx.x;

    {
        const float4* src = (const float4*)(g_Y + (size_t)t * (H_ * B_));
        float4* dst = (float4*)ys;
        #pragma unroll
        for (int i = 0; i < 16; ++i) dst[tid + i * 256] = src[tid + i * 256];
        const float4* ps = (const float4*)pW;
        float4* pd = (float4*)pWs;
        #pragma unroll
        for (int i = 0; i < 25; ++i) pd[tid + i * 256] = ps[tid + i * 256];
    }
    __syncthreads();

    {
        int b = tid & 31, l0 = tid >> 5;
        for (int l = l0; l < 50; l += 8) {
            float s = __ldg(&pb[l]);
            #pragma unroll 8
            for (int h = 0; h < 512; ++h) s += ys[h * 32 + b] * pWs[h * 50 + l];
            lg[l * 32 + b] = fmaxf(s, 0.f);
        }
    }
    __syncthreads();

    if (tid < 32) {
        int b = tid;
        if (t < __ldg(&lengths[b])) {
            float mx = lg[b];
            #pragma unroll
            for (int l = 1; l < 50; ++l) mx = fmaxf(mx, lg[l * 32 + b]);
            float se = 0.f;
            #pragma unroll
            for (int l = 0; l < 50; ++l) se += expf(lg[l * 32 + b] - mx);
            float lse = logf(se) + mx;
            int lab = __ldg(&a[(b << 9) + t]);
            atomicAdd(&g_acc[b], lse - lg[lab * 32 + b]);
        }
    }
}

__global__ void final_kernel(const int* __restrict__ lengths, float* __restrict__ out) {
    if (threadIdx.x == 0) {
        float s = 0.f;
        for (int b = 0; b < B_; ++b) s += g_acc[b] / (float)lengths[b];
        out[0] = s * (1.f / (float)B_);
    }
}

// ---------------- launch ----------------------------------------------------------
extern "C" void kernel_launch(void* const* d_in, const int* in_sizes, int n_in,
                              void* d_out, int out_size) {
    const int*   q       = (const int*)d_in[0];
    const int*   a       = (const int*)d_in[1];
    const int*   lengths = (const int*)d_in[2];
    const float* we      = (const float*)d_in[3];
    const float* W       = (const float*)d_in[4];
    const float* bvec    = (const float*)d_in[5];
    const float* pW      = (const float*)d_in[6];
    const float* pb      = (const float*)d_in[7];
    float* out = (float*)d_out;

    cudaFuncSetAttribute(zx_kernel, cudaFuncAttributeMaxDynamicSharedMemorySize, ZX_SMEM);
    cudaFuncSetAttribute(lstm_kernel, cudaFuncAttributeMaxDynamicSharedMemorySize, SMEM_TOTAL);
    cudaFuncSetAttribute(loss_kernel, cudaFuncAttributeMaxDynamicSharedMemorySize, LOSS_SMEM);

    zx_kernel<<<T_ * 4, 256, ZX_SMEM>>>(q, we, W, bvec);
    lstm_kernel<<<NB, NT, SMEM_TOTAL>>>(lengths, W);
    loss_kernel<<<T_, 256, LOSS_SMEM>>>(a, lengths, pW, pb);
    final_kernel<<<1, 32>>>(lengths, out);
}